// round 12
// baseline (speedup 1.0000x reference)
#include <cuda_runtime.h>
#include <math.h>
#include <stdint.h>

#define NUM_CLASSES 10
#define PV 15                          // floats per cell
#define THREADS 128
#define WPC 4                          // warps per CTA
#define WT_CELLS 32                    // cells per warp-tile
#define WT_BYTES (WT_CELLS * PV * 4)   // 1920 bytes per array per warp-tile
#define TOTAL_CELLS (2048 * 26 * 26)   // 1,384,448
#define NWT (TOTAL_CELLS / WT_CELLS)   // 43,264 warp-tiles (exact)
#define STAGES 3
#define GRID 592                       // 148 SMs * 4 CTAs
#define GWARPS (GRID * WPC)            // 2368 warp pipelines
#define LAMBDA_COORD 5.0f
#define LAMBDA_NOOBJ 0.5f

// Accumulators + completion counter. Zero at module load; reset by the
// finalizing block each call (graph-replay safe).
__device__ double g_acc[3];
__device__ unsigned int g_count;

__global__ __launch_bounds__(THREADS)
void yolo_fused_kernel(const float* __restrict__ pred,
                       const float* __restrict__ tgt,
                       float* __restrict__ out) {
    // Per-warp private triple-buffered tiles: [warp][stage][0]=pred,[1]=tgt
    __shared__ __align__(16) float sbuf[WPC][STAGES][2][WT_CELLS * PV]; // 46,080 B
    __shared__ __align__(8) unsigned long long mbar[WPC][STAGES];      // 12 mbarriers
    __shared__ float red[3][WPC];
    __shared__ bool s_is_last;

    const int tid  = threadIdx.x;
    const int wid  = tid >> 5;
    const int lane = tid & 31;

    const uint32_t mb_base = (uint32_t)__cvta_generic_to_shared(&mbar[0][0]);
    const uint32_t sb_base = (uint32_t)__cvta_generic_to_shared(&sbuf[0][0][0][0]);

    // Init all mbarriers once (arrive count = 1: the expect_tx arrive).
    if (tid == 0) {
        #pragma unroll
        for (int i = 0; i < WPC * STAGES; i++) {
            asm volatile("mbarrier.init.shared.b64 [%0], 1;"
                         :: "r"(mb_base + (uint32_t)i * 8u) : "memory");
        }
    }
    __syncthreads();

    // Issue one warp-tile via two bulk copies (elected lane only).
    auto issue = [&](long long wt, int st) {
        if (wt < (long long)NWT && lane == 0) {
            const uint32_t mb = mb_base + (uint32_t)(wid * STAGES + st) * 8u;
            const uint32_t dp = sb_base
                + (uint32_t)((wid * STAGES + st) * 2 * WT_BYTES);
            const uint32_t dt = dp + (uint32_t)WT_BYTES;
            const char* sp = (const char*)pred + (size_t)wt * WT_BYTES;
            const char* sq = (const char*)tgt  + (size_t)wt * WT_BYTES;
            asm volatile("mbarrier.arrive.expect_tx.shared.b64 _, [%0], %1;"
                         :: "r"(mb), "r"(2 * WT_BYTES) : "memory");
            asm volatile("cp.async.bulk.shared::cta.global.mbarrier::complete_tx::bytes"
                         " [%0], [%1], %2, [%3];"
                         :: "r"(dp), "l"(sp), "r"(WT_BYTES), "r"(mb) : "memory");
            asm volatile("cp.async.bulk.shared::cta.global.mbarrier::complete_tx::bytes"
                         " [%0], [%1], %2, [%3];"
                         :: "r"(dt), "l"(sq), "r"(WT_BYTES), "r"(mb) : "memory");
        }
    };

    const long long gw = (long long)blockIdx.x * WPC + wid;   // global warp id
    float acc0 = 0.0f, acc1 = 0.0f, acc2 = 0.0f;

    // ---- Prologue: issue STAGES warp-tiles ----
    #pragma unroll
    for (int s = 0; s < STAGES; s++) issue(gw + (long long)s * GWARPS, s);

    // ---- Main loop: fully warp-independent ----
    long long wt = gw;
    for (int k = 0; wt < (long long)NWT; wt += GWARPS, k++) {
        const int st = k % STAGES;
        const uint32_t ph = (uint32_t)((k / STAGES) & 1);
        const uint32_t mb = mb_base + (uint32_t)(wid * STAGES + st) * 8u;

        // Wait for this stage's bulk copies (acquire orders subsequent LDS).
        {
            uint32_t done;
            asm volatile(
                "{\n\t.reg .pred p;\n\t"
                "mbarrier.try_wait.parity.acquire.cta.shared::cta.b64 p, [%1], %2;\n\t"
                "selp.b32 %0, 1, 0, p;\n\t}"
                : "=r"(done) : "r"(mb), "r"(ph) : "memory");
            while (!done) {
                asm volatile(
                    "{\n\t.reg .pred p;\n\t"
                    "mbarrier.try_wait.parity.acquire.cta.shared::cta.b64 p, [%1], %2, 0x989680;\n\t"
                    "selp.b32 %0, 1, 0, p;\n\t}"
                    : "=r"(done) : "r"(mb), "r"(ph) : "memory");
            }
        }

        const float* p = &sbuf[wid][st][0][0] + lane * PV;
        const float* q = &sbuf[wid][st][1][0] + lane * PV;

        float t_conf = q[4];
        bool  obj    = t_conf > 0.0f;

        float coord_sq = 0.0f;
        #pragma unroll
        for (int j = 0; j < 4; j++) {
            float d = p[j] - q[j];
            coord_sq += d * d;
        }

        float conf_p = 1.0f / (1.0f + __expf(-p[4]));

        float cls_sq = 0.0f;
        #pragma unroll
        for (int j = 5; j < 5 + NUM_CLASSES; j++) {
            float d = p[j] - q[j];
            cls_sq += d * d;
        }
        cls_sq *= (1.0f / (float)NUM_CLASSES);

        float dconf = conf_p - t_conf;
        acc0 += obj ? LAMBDA_COORD * coord_sq : 0.0f;
        acc1 += obj ? dconf * dconf : LAMBDA_NOOBJ * conf_p * conf_p;
        acc2 += obj ? cls_sq : 0.0f;

        __syncwarp();          // WAR: all lanes' reads done before refill
        issue(wt + (long long)STAGES * GWARPS, st);
    }

    // ---- Warp reduction, then CTA reduction ----
    #pragma unroll
    for (int off = 16; off > 0; off >>= 1) {
        acc0 += __shfl_xor_sync(0xFFFFFFFFu, acc0, off);
        acc1 += __shfl_xor_sync(0xFFFFFFFFu, acc1, off);
        acc2 += __shfl_xor_sync(0xFFFFFFFFu, acc2, off);
    }
    if (lane == 0) {
        red[0][wid] = acc0;
        red[1][wid] = acc1;
        red[2][wid] = acc2;
    }
    __syncthreads();

    if (tid == 0) {
        float a = 0.0f, b = 0.0f, c = 0.0f;
        #pragma unroll
        for (int w = 0; w < WPC; w++) {
            a += red[0][w]; b += red[1][w]; c += red[2][w];
        }
        atomicAdd(&g_acc[0], (double)a);
        atomicAdd(&g_acc[1], (double)b);
        atomicAdd(&g_acc[2], (double)c);
        __threadfence();
        unsigned int prev = atomicAdd(&g_count, 1u);
        s_is_last = (prev == (unsigned int)(GRID - 1));
    }
    __syncthreads();

    // ---- Last block: finalize output, reset state for next replay ----
    if (s_is_last && tid == 0) {
        volatile double* acc = g_acc;
        double c = acc[0], f = acc[1], l = acc[2];
        out[0] = (float)(c + f + l);   // total
        out[1] = (float)c;             // coord
        out[2] = (float)f;             // conf
        out[3] = (float)l;             // class
        g_acc[0] = 0.0;
        g_acc[1] = 0.0;
        g_acc[2] = 0.0;
        g_count  = 0u;
    }
}

extern "C" void kernel_launch(void* const* d_in, const int* in_sizes, int n_in,
                              void* d_out, int out_size) {
    const float* pred = (const float*)d_in[0];
    const float* tgt  = (const float*)d_in[1];
    float* out = (float*)d_out;

    yolo_fused_kernel<<<GRID, THREADS>>>(pred, tgt, out);
}